// round 12
// baseline (speedup 1.0000x reference)
#include <cuda_runtime.h>
#include <cuda_bf16.h>
#include <cuda_fp16.h>
#include <math.h>
#include <stdint.h>

#define DI __device__ __forceinline__

namespace {
constexpr int Bn = 16;
constexpr int Sn = 2048;
constexpr int Hn = 128;
constexpr int Dn = 64;
constexpr float SHIFT = 8.0f;
constexpr float ECLAMP = 60000.0f;
constexpr int NPAD = 136;
constexpr int QKS = 72;          // stride (halves); 144B rows -> LDSM conflict-free
constexpr int KT  = 128;         // k-cols per CTA
constexpr int QI  = 64;          // q-rows per iteration
constexpr int ESW = 136;         // E smem stride (halves); 272B rows -> STSM conflict-free
constexpr int ESBUF = QI * ESW;  // halves per E buffer
constexpr int QBUF = 2 * QI * QKS;   // halves per Q double-buffer entry (hi+lo)
}

__device__ __nv_bfloat16 g_Wh[NPAD * Hn];      // fused weight hi/lo (bf16, for k_qku)
__device__ __nv_bfloat16 g_Wl[NPAD * Hn];
__device__ float         g_PE[Sn * Hn];
__device__ __half        g_Qh[Bn * Sn * Dn];   // Q/8 fp16 hi
__device__ __half        g_Ql[Bn * Sn * Dn];   // Q/8 fp16 lo (22-bit combined)
__device__ __half        g_Kf[Bn * Sn * Dn];   // K fp16 (single)
__device__ float         g_u[Bn * Sn];
__device__ float         g_t[Bn * Sn];
__device__ __half        g_E[(size_t)Bn * Sn * Sn];   // 134MB exp(s-SHIFT) fp16

DI uint32_t ld32(const __nv_bfloat16* p) { return *(const uint32_t*)p; }

DI void mma_bf16(float* c, uint32_t a0, uint32_t a1, uint32_t a2, uint32_t a3,
                 uint32_t b0, uint32_t b1) {
    asm volatile(
        "mma.sync.aligned.m16n8k16.row.col.f32.bf16.bf16.f32 "
        "{%0,%1,%2,%3}, {%4,%5,%6,%7}, {%8,%9}, {%0,%1,%2,%3};\n"
        : "+f"(c[0]), "+f"(c[1]), "+f"(c[2]), "+f"(c[3])
        : "r"(a0), "r"(a1), "r"(a2), "r"(a3), "r"(b0), "r"(b1));
}

DI void mma_f16(float* c, uint32_t a0, uint32_t a1, uint32_t a2, uint32_t a3,
                uint32_t b0, uint32_t b1) {
    asm volatile(
        "mma.sync.aligned.m16n8k16.row.col.f32.f16.f16.f32 "
        "{%0,%1,%2,%3}, {%4,%5,%6,%7}, {%8,%9}, {%0,%1,%2,%3};\n"
        : "+f"(c[0]), "+f"(c[1]), "+f"(c[2]), "+f"(c[3])
        : "r"(a0), "r"(a1), "r"(a2), "r"(a3), "r"(b0), "r"(b1));
}

DI void ldsm4(uint32_t addr, uint32_t& r0, uint32_t& r1, uint32_t& r2, uint32_t& r3) {
    asm volatile("ldmatrix.sync.aligned.m8n8.x4.shared.b16 {%0,%1,%2,%3}, [%4];\n"
                 : "=r"(r0), "=r"(r1), "=r"(r2), "=r"(r3) : "r"(addr));
}

DI void stsm4(uint32_t addr, uint32_t r0, uint32_t r1, uint32_t r2, uint32_t r3) {
    asm volatile("stmatrix.sync.aligned.m8n8.x4.shared.b16 [%0], {%1,%2,%3,%4};\n"
                 :: "r"(addr), "r"(r0), "r"(r1), "r"(r2), "r"(r3) : "memory");
}

DI void cpa16(uint32_t dst, const void* src) {
    asm volatile("cp.async.ca.shared.global [%0], [%1], 16;\n" :: "r"(dst), "l"(src));
}
DI void cpa_commit() { asm volatile("cp.async.commit_group;\n" ::: "memory"); }
DI void cpa_wait0()  { asm volatile("cp.async.wait_group 0;\n" ::: "memory"); }

DI void split2(float a, float b, __nv_bfloat162* hd, __nv_bfloat162* ld) {
    __nv_bfloat162 h = __floats2bfloat162_rn(a, b);
    float ra = a - __low2float(h);
    float rb = b - __high2float(h);
    *hd = h;
    *ld = __floats2bfloat162_rn(ra, rb);
}

DI void split2h(float a, float b, __half2* hd, __half2* ld) {
    __half2 h = __floats2half2_rn(a, b);
    float ra = a - __low2float(h);
    float rb = b - __high2float(h);
    *hd = h;
    *ld = __floats2half2_rn(ra, rb);
}

// ---------------- K0a: positional encoding ----------------
__global__ void k_pe() {
    int idx = blockIdx.x * blockDim.x + threadIdx.x;
    if (idx >= Sn * (Hn / 2)) return;
    int p = idx >> 6;
    int j = idx & 63;
    double fac = pow(10000.0, (double)j / 64.0);
    float ang = (float)((double)p / fac);
    float sv, cv;
    sincosf(ang, &sv, &cv);
    g_PE[p * Hn + 2 * j]     = sv;
    g_PE[p * Hn + 2 * j + 1] = cv;
}

// ---------------- K0b: fused transposed weight, bf16 hi/lo ----------------
__global__ void k_wcat(const float* __restrict__ Wq, const float* __restrict__ Wk,
                       const float* __restrict__ Wv, const float* __restrict__ Wf) {
    int idx = blockIdx.x * blockDim.x + threadIdx.x;
    if (idx >= NPAD * Hn) return;
    int n = idx >> 7;
    int h = idx & 127;
    float v = 0.0f;
    if (n < 64) {
        v = Wq[h * Dn + n] * 0.125f;
    } else if (n < 128) {
        v = Wk[h * Dn + (n - 64)];
    } else if (n == 128) {
        float s = 0.0f;
        for (int d = 0; d < Dn; ++d) s += Wv[h * Dn + d] * Wf[d];
        v = s;
    }
    __nv_bfloat16 hb = __float2bfloat16(v);
    g_Wh[n * Hn + h] = hb;
    g_Wl[n * Hn + h] = __float2bfloat16(v - __bfloat162float(hb));
}

// ---------------- K1: xp = x + PE; Q(hi/lo fp16), K(fp16), u via bf16x3 GEMM ----------------
__global__ void k_qku(const float* __restrict__ x) {
    extern __shared__ __nv_bfloat16 sm[];
    __nv_bfloat16* Ash = sm;
    __nv_bfloat16* Asl = Ash + 128 * NPAD;
    __nv_bfloat16* Bsh = Asl + 128 * NPAD;
    __nv_bfloat16* Bsl = Bsh + NPAD * NPAD;

    int tid = threadIdx.x;
    int r0 = blockIdx.x * 128;
    int srow0 = r0 & (Sn - 1);

    const float4* x4 = (const float4*)x;
    for (int i = tid; i < 128 * 32; i += 256) {
        int row = i >> 5, c4 = i & 31;
        float4 v = x4[(size_t)(r0 + row) * 32 + c4];
        const float* pe = &g_PE[(srow0 + row) * Hn + c4 * 4];
        v.x += pe[0]; v.y += pe[1]; v.z += pe[2]; v.w += pe[3];
        __nv_bfloat162* dh = (__nv_bfloat162*)&Ash[row * NPAD + c4 * 4];
        __nv_bfloat162* dl = (__nv_bfloat162*)&Asl[row * NPAD + c4 * 4];
        split2(v.x, v.y, &dh[0], &dl[0]);
        split2(v.z, v.w, &dh[1], &dl[1]);
    }
    for (int i = tid; i < NPAD * Hn; i += 256) {
        int n = i >> 7, h = i & 127;
        Bsh[n * NPAD + h] = g_Wh[i];
        Bsl[n * NPAD + h] = g_Wl[i];
    }
    __syncthreads();

    int warp = tid >> 5, lane = tid & 31;
    int g = lane >> 2, t = lane & 3;
    int rw = warp * 16;

    float acc[17][4];
#pragma unroll
    for (int nt = 0; nt < 17; nt++)
#pragma unroll
        for (int i = 0; i < 4; i++) acc[nt][i] = 0.0f;

#pragma unroll
    for (int ks = 0; ks < 8; ks++) {
        int kb = ks * 16;
        uint32_t ah0 = ld32(&Ash[(rw + g) * NPAD + kb + 2 * t]);
        uint32_t ah1 = ld32(&Ash[(rw + g + 8) * NPAD + kb + 2 * t]);
        uint32_t ah2 = ld32(&Ash[(rw + g) * NPAD + kb + 2 * t + 8]);
        uint32_t ah3 = ld32(&Ash[(rw + g + 8) * NPAD + kb + 2 * t + 8]);
        uint32_t al0 = ld32(&Asl[(rw + g) * NPAD + kb + 2 * t]);
        uint32_t al1 = ld32(&Asl[(rw + g + 8) * NPAD + kb + 2 * t]);
        uint32_t al2 = ld32(&Asl[(rw + g) * NPAD + kb + 2 * t + 8]);
        uint32_t al3 = ld32(&Asl[(rw + g + 8) * NPAD + kb + 2 * t + 8]);
#pragma unroll
        for (int nt = 0; nt < 17; nt++) {
            uint32_t bh0 = ld32(&Bsh[(nt * 8 + g) * NPAD + kb + 2 * t]);
            uint32_t bh1 = ld32(&Bsh[(nt * 8 + g) * NPAD + kb + 2 * t + 8]);
            uint32_t bl0 = ld32(&Bsl[(nt * 8 + g) * NPAD + kb + 2 * t]);
            uint32_t bl1 = ld32(&Bsl[(nt * 8 + g) * NPAD + kb + 2 * t + 8]);
            mma_bf16(acc[nt], ah0, ah1, ah2, ah3, bh0, bh1);
            mma_bf16(acc[nt], ah0, ah1, ah2, ah3, bl0, bl1);
            mma_bf16(acc[nt], al0, al1, al2, al3, bh0, bh1);
        }
    }

    int rA = r0 + rw + g, rB = rA + 8;
#pragma unroll
    for (int nt = 0; nt < 17; nt++) {
        int col = nt * 8 + 2 * t;
        if (col < 64) {
            split2h(acc[nt][0], acc[nt][1],
                    (__half2*)&g_Qh[(size_t)rA * Dn + col],
                    (__half2*)&g_Ql[(size_t)rA * Dn + col]);
            split2h(acc[nt][2], acc[nt][3],
                    (__half2*)&g_Qh[(size_t)rB * Dn + col],
                    (__half2*)&g_Ql[(size_t)rB * Dn + col]);
        } else if (col < 128) {
            *(__half2*)&g_Kf[(size_t)rA * Dn + col - 64] =
                __floats2half2_rn(acc[nt][0], acc[nt][1]);
            *(__half2*)&g_Kf[(size_t)rB * Dn + col - 64] =
                __floats2half2_rn(acc[nt][2], acc[nt][3]);
        } else if (col == 128) {
            g_u[rA] = acc[nt][0];
            g_u[rB] = acc[nt][2];
        }
    }
}

// ---------------- K2 v6: STSM epilogue, double-buffered E, 1 sync/iter ----------------
// CTA: 128 k-cols x all 2048 q (32 iters of 64 q-rows). Grid 16x16 = 256, 2 CTA/SM.
__global__ __launch_bounds__(512, 2) void k_zt6() {
    extern __shared__ __half sm2[];
    __half* Ks  = sm2;                       // [128][QKS] single fp16
    __half* Qb  = Ks + KT * QKS;             // [2 bufs][hi/lo][64][QKS]
    __half* Es0 = Qb + 2 * QBUF;             // [2 bufs][64][ESW]
    __shared__ float zred[16][32];

    int tid = threadIdx.x;
    int b = blockIdx.y;
    int kg0 = blockIdx.x * KT;

    size_t qbase = (size_t)b * Sn * Dn;
    uint32_t qsm = (uint32_t)__cvta_generic_to_shared(Qb);
    uint32_t esm = (uint32_t)__cvta_generic_to_shared(Es0);

    // ---- preload Q iter 0 via cp.async ----
    {
#pragma unroll
        for (int j = 0; j < 2; j++) {
            int flat = tid + 512 * j;
            int hl = flat >> 9, rem = flat & 511, row = rem >> 3, seg = rem & 7;
            const __half* src = (hl ? g_Ql : g_Qh) + qbase + (size_t)row * Dn + seg * 8;
            cpa16(qsm + (uint32_t)(hl * QI * QKS + row * QKS + seg * 8) * 2, src);
        }
        cpa_commit();
    }

    // ---- stage K tile (single fp16) ----
    {
        size_t base = ((size_t)b * Sn + kg0) * Dn;
        const uint32_t* Kg = (const uint32_t*)&g_Kf[base];
        for (int i = tid; i < KT * 32; i += 512) {
            int row = i >> 5, p = i & 31;
            *(uint32_t*)&Ks[row * QKS + 2 * p] = Kg[row * 32 + p];
        }
    }

    int warp = tid >> 5, lane = tid & 31;
    int mw = warp & 3, nw = warp >> 2;
    int g = lane >> 2, t = lane & 3;
    int rw = mw * 16;

    // ldmatrix addresses
    uint32_t aOffHalves = (uint32_t)((rw + (lane & 15)) * QKS + ((lane >> 4) << 3));
    uint32_t ksmB = (uint32_t)__cvta_generic_to_shared(Ks)
                  + (uint32_t)(((nw * 32 + (lane & 7) + ((lane >> 4) << 3)) * QKS
                                + (((lane >> 3) & 1) << 3)) * 2);

    // stmatrix addresses: matrix j = lane>>3 (cols +8j), row r = lane&7
    uint32_t esOffA = (uint32_t)(((rw + (lane & 7)) * ESW
                                  + nw * 32 + ((lane >> 3) << 3)) * 2);
    uint32_t esOffB = esOffA + (uint32_t)(8 * ESW * 2);

    float z0[4], z1[4];
#pragma unroll
    for (int nt = 0; nt < 4; nt++) { z0[nt] = 0.0f; z1[nt] = 0.0f; }

    for (int qc = 0; qc < 32; qc++) {
        cpa_wait0();
        __syncthreads();   // Q[qc] visible; all STSM of iter qc-1 visible; drains of qc-1 done

        // drain E tile of iter qc-1 (other buffer) -> overlaps with this iter's MMA
        if (qc > 0) {
            const __half* Ed = Es0 + ((qc - 1) & 1) * ESBUF;
            size_t growBase = ((size_t)(b * Sn + (qc - 1) * QI)) * Sn + kg0;
#pragma unroll
            for (int j = 0; j < 2; j++) {
                int flat = tid + 512 * j;
                int r = flat >> 4, seg = flat & 15;
                uint4 v = *(const uint4*)&Ed[r * ESW + seg * 8];
                *(uint4*)&g_E[growBase + (size_t)r * Sn + seg * 8] = v;
            }
        }

        if (qc + 1 < 32) {   // prefetch Q[qc+1] into other buffer
            int nbuf = (qc + 1) & 1;
            size_t qoff = qbase + (size_t)(qc + 1) * QI * Dn;
#pragma unroll
            for (int j = 0; j < 2; j++) {
                int flat = tid + 512 * j;
                int hl = flat >> 9, rem = flat & 511, row = rem >> 3, seg = rem & 7;
                const __half* src = (hl ? g_Ql : g_Qh) + qoff + (size_t)row * Dn + seg * 8;
                cpa16(qsm + (uint32_t)(nbuf * QBUF + hl * QI * QKS + row * QKS + seg * 8) * 2, src);
            }
            cpa_commit();
        }

        int buf = qc & 1;
        uint32_t aH = qsm + (uint32_t)(buf * QBUF + aOffHalves) * 2;
        uint32_t aL = aH + (uint32_t)(QI * QKS * 2);

        float acc[4][4];
#pragma unroll
        for (int nt = 0; nt < 4; nt++)
#pragma unroll
            for (int i = 0; i < 4; i++) acc[nt][i] = 0.0f;

#pragma unroll
        for (int ks = 0; ks < 4; ks++) {
            uint32_t kbB = ks * 32;
            uint32_t ah0, ah1, ah2, ah3, al0, al1, al2, al3;
            ldsm4(aH + kbB, ah0, ah1, ah2, ah3);
            ldsm4(aL + kbB, al0, al1, al2, al3);
#pragma unroll
            for (int p = 0; p < 2; p++) {
                uint32_t bo = (uint32_t)(p * 16 * QKS * 2) + kbB;
                uint32_t b0, b1, b2, b3;
                ldsm4(ksmB + bo, b0, b1, b2, b3);
                mma_f16(acc[2 * p],     ah0, ah1, ah2, ah3, b0, b1);
                mma_f16(acc[2 * p],     al0, al1, al2, al3, b0, b1);
                mma_f16(acc[2 * p + 1], ah0, ah1, ah2, ah3, b2, b3);
                mma_f16(acc[2 * p + 1], al0, al1, al2, al3, b2, b3);
            }
        }

        // exp -> pack -> 2x stmatrix into Es[qc&1]; Z from rounded values
        uint32_t hA[4], hB[4];
#pragma unroll
        for (int nt = 0; nt < 4; nt++) {
            float e0 = fminf(__expf(acc[nt][0] - SHIFT), ECLAMP);
            float e1 = fminf(__expf(acc[nt][1] - SHIFT), ECLAMP);
            float e2 = fminf(__expf(acc[nt][2] - SHIFT), ECLAMP);
            float e3 = fminf(__expf(acc[nt][3] - SHIFT), ECLAMP);
            __half2 h01 = __floats2half2_rn(e0, e1);
            __half2 h23 = __floats2half2_rn(e2, e3);
            hA[nt] = *(uint32_t*)&h01;
            hB[nt] = *(uint32_t*)&h23;
            float2 f01 = __half22float2(h01);
            float2 f23 = __half22float2(h23);
            z0[nt] += f01.x + f23.x;
            z1[nt] += f01.y + f23.y;
        }
        uint32_t esW = esm + (uint32_t)(buf * ESBUF * 2);
        stsm4(esW + esOffA, hA[0], hA[1], hA[2], hA[3]);
        stsm4(esW + esOffB, hB[0], hB[1], hB[2], hB[3]);
    }

    // tail: drain last E tile
    __syncthreads();
    {
        const __half* Ed = Es0 + (31 & 1) * ESBUF;
        size_t growBase = ((size_t)(b * Sn + 31 * QI)) * Sn + kg0;
#pragma unroll
        for (int j = 0; j < 2; j++) {
            int flat = tid + 512 * j;
            int r = flat >> 4, seg = flat & 15;
            uint4 v = *(const uint4*)&Ed[r * ESW + seg * 8];
            *(uint4*)&g_E[growBase + (size_t)r * Sn + seg * 8] = v;
        }
    }

    // ---- Z reduction ----
#pragma unroll
    for (int nt = 0; nt < 4; nt++) {
        z0[nt] += __shfl_xor_sync(0xffffffffu, z0[nt], 4);
        z0[nt] += __shfl_xor_sync(0xffffffffu, z0[nt], 8);
        z0[nt] += __shfl_xor_sync(0xffffffffu, z0[nt], 16);
        z1[nt] += __shfl_xor_sync(0xffffffffu, z1[nt], 4);
        z1[nt] += __shfl_xor_sync(0xffffffffu, z1[nt], 8);
        z1[nt] += __shfl_xor_sync(0xffffffffu, z1[nt], 16);
    }
    if (lane < 4) {
#pragma unroll
        for (int nt = 0; nt < 4; nt++) {
            zred[warp][nt * 8 + 2 * lane]     = z0[nt];
            zred[warp][nt * 8 + 2 * lane + 1] = z1[nt];
        }
    }
    __syncthreads();
    if (tid < 128) {
        int c = tid;
        float Z = 0.0f;
#pragma unroll
        for (int m = 0; m < 4; m++) Z += zred[(c >> 5) * 4 + m][c & 31];
        int kg = b * Sn + kg0 + c;
        g_t[kg] = g_u[kg] / Z;
    }
}

// ---------------- K3: memory-bound GEMV ----------------
__global__ void k_gemv(const float* __restrict__ bfp, float* __restrict__ out) {
    __shared__ float ts[Sn];
    int tid = threadIdx.x;
    int b = blockIdx.y;
    int q0 = blockIdx.x * 32;

    for (int i = tid; i < Sn; i += 256) ts[i] = g_t[b * Sn + i];
    __syncthreads();

    int warp = tid >> 5, lane = tid & 31;
    float bias = bfp[0];

#pragma unroll
    for (int rr = 0; rr < 4; rr++) {
        int q = q0 + warp * 4 + rr;
        const uint4* Erow = (const uint4*)&g_E[((size_t)b * Sn + q) * Sn];
        float acc = 0.0f;
#pragma unroll
        for (int j = 0; j < 8; j++) {
            uint4 v = Erow[j * 32 + lane];
            const float2* tp = (const float2*)&ts[j * 256 + lane * 8];
            float2 f, tt;
            f = __half22float2(*(__half2*)&v.x); tt = tp[0]; acc += f.x * tt.x + f.y * tt.y;
            f = __half22float2(*(__half2*)&v.y); tt = tp[1]; acc += f.x * tt.x + f.y * tt.y;
            f = __half22float2(*(__half2*)&v.z); tt = tp[2]; acc += f.x * tt.x + f.y * tt.y;
            f = __half22float2(*(__half2*)&v.w); tt = tp[3]; acc += f.x * tt.x + f.y * tt.y;
        }
        acc += __shfl_xor_sync(0xffffffffu, acc, 16);
        acc += __shfl_xor_sync(0xffffffffu, acc, 8);
        acc += __shfl_xor_sync(0xffffffffu, acc, 4);
        acc += __shfl_xor_sync(0xffffffffu, acc, 2);
        acc += __shfl_xor_sync(0xffffffffu, acc, 1);
        if (lane == 0) out[b * Sn + q] = acc + bias;
    }
}

extern "C" void kernel_launch(void* const* d_in, const int* in_sizes, int n_in,
                              void* d_out, int out_size) {
    (void)in_sizes; (void)n_in; (void)out_size;
    const float* x  = (const float*)d_in[0];
    const float* Wq = (const float*)d_in[1];
    const float* Wk = (const float*)d_in[2];
    const float* Wv = (const float*)d_in[3];
    const float* Wf = (const float*)d_in[4];
    const float* bf = (const float*)d_in[5];
    float* out = (float*)d_out;

    const int smem_k1 = (2 * 128 * NPAD + 2 * NPAD * NPAD) * (int)sizeof(__nv_bfloat16);
    const int smem_k2 = (KT * QKS + 2 * QBUF + 2 * ESBUF) * (int)sizeof(__half);
    cudaFuncSetAttribute(k_qku, cudaFuncAttributeMaxDynamicSharedMemorySize, smem_k1);
    cudaFuncSetAttribute(k_zt6, cudaFuncAttributeMaxDynamicSharedMemorySize, smem_k2);

    k_pe<<<(Sn * (Hn / 2) + 255) / 256, 256>>>();
    k_wcat<<<(NPAD * Hn + 255) / 256, 256>>>(Wq, Wk, Wv, Wf);
    k_qku<<<Bn * Sn / 128, 256, smem_k1>>>(x);
    k_zt6<<<dim3(Sn / KT, Bn), 512, smem_k2>>>();
    k_gemv<<<dim3(Sn / 32, Bn), 256>>>(bf, out);
}

// round 14
// speedup vs baseline: 1.6166x; 1.6166x over previous
#include <cuda_runtime.h>
#include <cuda_bf16.h>
#include <cuda_fp16.h>
#include <math.h>
#include <stdint.h>

#define DI __device__ __forceinline__

namespace {
constexpr int Bn = 16;
constexpr int Sn = 2048;
constexpr int Hn = 128;
constexpr int Dn = 64;
constexpr float SHIFT = 8.0f;
constexpr float ECLAMP = 60000.0f;
constexpr int NPAD = 136;
constexpr int QKS = 72;          // stride (halves); 144B rows -> LDSM conflict-free
constexpr int KT  = 128;         // k-cols per CTA
constexpr int QI  = 64;          // q-rows per iteration
constexpr int ESW = 136;         // E smem stride (halves)
constexpr int QBUF = QI * QKS;   // halves per Q double-buffer entry (single fp16)
}

__device__ __nv_bfloat16 g_Wh[NPAD * Hn];      // fused weight hi/lo (bf16, for k_qku)
__device__ __nv_bfloat16 g_Wl[NPAD * Hn];
__device__ float         g_PE[Sn * Hn];
__device__ __half        g_Qf[Bn * Sn * Dn];   // Q/8 fp16 (single)
__device__ __half        g_Kf[Bn * Sn * Dn];   // K fp16 (single)
__device__ float         g_u[Bn * Sn];
__device__ float         g_t[Bn * Sn];
__device__ __half        g_E[(size_t)Bn * Sn * Sn];   // 134MB exp(s-SHIFT) fp16

DI uint32_t ld32(const __nv_bfloat16* p) { return *(const uint32_t*)p; }

DI void mma_bf16(float* c, uint32_t a0, uint32_t a1, uint32_t a2, uint32_t a3,
                 uint32_t b0, uint32_t b1) {
    asm volatile(
        "mma.sync.aligned.m16n8k16.row.col.f32.bf16.bf16.f32 "
        "{%0,%1,%2,%3}, {%4,%5,%6,%7}, {%8,%9}, {%0,%1,%2,%3};\n"
        : "+f"(c[0]), "+f"(c[1]), "+f"(c[2]), "+f"(c[3])
        : "r"(a0), "r"(a1), "r"(a2), "r"(a3), "r"(b0), "r"(b1));
}

DI void mma_f16(float* c, uint32_t a0, uint32_t a1, uint32_t a2, uint32_t a3,
                uint32_t b0, uint32_t b1) {
    asm volatile(
        "mma.sync.aligned.m16n8k16.row.col.f32.f16.f16.f32 "
        "{%0,%1,%2,%3}, {%4,%5,%6,%7}, {%8,%9}, {%0,%1,%2,%3};\n"
        : "+f"(c[0]), "+f"(c[1]), "+f"(c[2]), "+f"(c[3])
        : "r"(a0), "r"(a1), "r"(a2), "r"(a3), "r"(b0), "r"(b1));
}

DI void ldsm4(uint32_t addr, uint32_t& r0, uint32_t& r1, uint32_t& r2, uint32_t& r3) {
    asm volatile("ldmatrix.sync.aligned.m8n8.x4.shared.b16 {%0,%1,%2,%3}, [%4];\n"
                 : "=r"(r0), "=r"(r1), "=r"(r2), "=r"(r3) : "r"(addr));
}

DI void cpa16(uint32_t dst, const void* src) {
    asm volatile("cp.async.ca.shared.global [%0], [%1], 16;\n" :: "r"(dst), "l"(src));
}
DI void cpa_commit() { asm volatile("cp.async.commit_group;\n" ::: "memory"); }
DI void cpa_wait0()  { asm volatile("cp.async.wait_group 0;\n" ::: "memory"); }

DI void split2(float a, float b, __nv_bfloat162* hd, __nv_bfloat162* ld) {
    __nv_bfloat162 h = __floats2bfloat162_rn(a, b);
    float ra = a - __low2float(h);
    float rb = b - __high2float(h);
    *hd = h;
    *ld = __floats2bfloat162_rn(ra, rb);
}

// ---------------- K0a: positional encoding ----------------
__global__ void k_pe() {
    int idx = blockIdx.x * blockDim.x + threadIdx.x;
    if (idx >= Sn * (Hn / 2)) return;
    int p = idx >> 6;
    int j = idx & 63;
    double fac = pow(10000.0, (double)j / 64.0);
    float ang = (float)((double)p / fac);
    float sv, cv;
    sincosf(ang, &sv, &cv);
    g_PE[p * Hn + 2 * j]     = sv;
    g_PE[p * Hn + 2 * j + 1] = cv;
}

// ---------------- K0b: fused transposed weight, bf16 hi/lo ----------------
__global__ void k_wcat(const float* __restrict__ Wq, const float* __restrict__ Wk,
                       const float* __restrict__ Wv, const float* __restrict__ Wf) {
    int idx = blockIdx.x * blockDim.x + threadIdx.x;
    if (idx >= NPAD * Hn) return;
    int n = idx >> 7;
    int h = idx & 127;
    float v = 0.0f;
    if (n < 64) {
        v = Wq[h * Dn + n] * 0.125f;
    } else if (n < 128) {
        v = Wk[h * Dn + (n - 64)];
    } else if (n == 128) {
        float s = 0.0f;
        for (int d = 0; d < Dn; ++d) s += Wv[h * Dn + d] * Wf[d];
        v = s;
    }
    __nv_bfloat16 hb = __float2bfloat16(v);
    g_Wh[n * Hn + h] = hb;
    g_Wl[n * Hn + h] = __float2bfloat16(v - __bfloat162float(hb));
}

// ---------------- K1: xp = x + PE; Q(fp16), K(fp16), u via bf16x3 GEMM ----------------
__global__ void k_qku(const float* __restrict__ x) {
    extern __shared__ __nv_bfloat16 sm[];
    __nv_bfloat16* Ash = sm;
    __nv_bfloat16* Asl = Ash + 128 * NPAD;
    __nv_bfloat16* Bsh = Asl + 128 * NPAD;
    __nv_bfloat16* Bsl = Bsh + NPAD * NPAD;

    int tid = threadIdx.x;
    int r0 = blockIdx.x * 128;
    int srow0 = r0 & (Sn - 1);

    const float4* x4 = (const float4*)x;
    for (int i = tid; i < 128 * 32; i += 256) {
        int row = i >> 5, c4 = i & 31;
        float4 v = x4[(size_t)(r0 + row) * 32 + c4];
        const float* pe = &g_PE[(srow0 + row) * Hn + c4 * 4];
        v.x += pe[0]; v.y += pe[1]; v.z += pe[2]; v.w += pe[3];
        __nv_bfloat162* dh = (__nv_bfloat162*)&Ash[row * NPAD + c4 * 4];
        __nv_bfloat162* dl = (__nv_bfloat162*)&Asl[row * NPAD + c4 * 4];
        split2(v.x, v.y, &dh[0], &dl[0]);
        split2(v.z, v.w, &dh[1], &dl[1]);
    }
    for (int i = tid; i < NPAD * Hn; i += 256) {
        int n = i >> 7, h = i & 127;
        Bsh[n * NPAD + h] = g_Wh[i];
        Bsl[n * NPAD + h] = g_Wl[i];
    }
    __syncthreads();

    int warp = tid >> 5, lane = tid & 31;
    int g = lane >> 2, t = lane & 3;
    int rw = warp * 16;

    float acc[17][4];
#pragma unroll
    for (int nt = 0; nt < 17; nt++)
#pragma unroll
        for (int i = 0; i < 4; i++) acc[nt][i] = 0.0f;

#pragma unroll
    for (int ks = 0; ks < 8; ks++) {
        int kb = ks * 16;
        uint32_t ah0 = ld32(&Ash[(rw + g) * NPAD + kb + 2 * t]);
        uint32_t ah1 = ld32(&Ash[(rw + g + 8) * NPAD + kb + 2 * t]);
        uint32_t ah2 = ld32(&Ash[(rw + g) * NPAD + kb + 2 * t + 8]);
        uint32_t ah3 = ld32(&Ash[(rw + g + 8) * NPAD + kb + 2 * t + 8]);
        uint32_t al0 = ld32(&Asl[(rw + g) * NPAD + kb + 2 * t]);
        uint32_t al1 = ld32(&Asl[(rw + g + 8) * NPAD + kb + 2 * t]);
        uint32_t al2 = ld32(&Asl[(rw + g) * NPAD + kb + 2 * t + 8]);
        uint32_t al3 = ld32(&Asl[(rw + g + 8) * NPAD + kb + 2 * t + 8]);
#pragma unroll
        for (int nt = 0; nt < 17; nt++) {
            uint32_t bh0 = ld32(&Bsh[(nt * 8 + g) * NPAD + kb + 2 * t]);
            uint32_t bh1 = ld32(&Bsh[(nt * 8 + g) * NPAD + kb + 2 * t + 8]);
            uint32_t bl0 = ld32(&Bsl[(nt * 8 + g) * NPAD + kb + 2 * t]);
            uint32_t bl1 = ld32(&Bsl[(nt * 8 + g) * NPAD + kb + 2 * t + 8]);
            mma_bf16(acc[nt], ah0, ah1, ah2, ah3, bh0, bh1);
            mma_bf16(acc[nt], ah0, ah1, ah2, ah3, bl0, bl1);
            mma_bf16(acc[nt], al0, al1, al2, al3, bh0, bh1);
        }
    }

    int rA = r0 + rw + g, rB = rA + 8;
#pragma unroll
    for (int nt = 0; nt < 17; nt++) {
        int col = nt * 8 + 2 * t;
        if (col < 64) {
            *(__half2*)&g_Qf[(size_t)rA * Dn + col] =
                __floats2half2_rn(acc[nt][0], acc[nt][1]);
            *(__half2*)&g_Qf[(size_t)rB * Dn + col] =
                __floats2half2_rn(acc[nt][2], acc[nt][3]);
        } else if (col < 128) {
            *(__half2*)&g_Kf[(size_t)rA * Dn + col - 64] =
                __floats2half2_rn(acc[nt][0], acc[nt][1]);
            *(__half2*)&g_Kf[(size_t)rB * Dn + col - 64] =
                __floats2half2_rn(acc[nt][2], acc[nt][3]);
        } else if (col == 128) {
            g_u[rA] = acc[nt][0];
            g_u[rB] = acc[nt][2];
        }
    }
}

// ---------------- K2 v7: single-fp16 QxK (1 MMA/tile), cp.async DB (R11 structure) ----------------
// CTA: 128 k-cols x all 2048 q (32 iters of 64 q-rows). Grid 16x16 = 256, 2 CTA/SM.
__global__ __launch_bounds__(512, 2) void k_zt7() {
    extern __shared__ __half sm2[];
    __half* Ks = sm2;                        // [128][QKS] single fp16
    __half* Qb = Ks + KT * QKS;              // [2 bufs][64][QKS] single fp16
    __half* Es = Qb + 2 * QBUF;              // [64][ESW]
    __shared__ float zred[16][32];

    int tid = threadIdx.x;
    int b = blockIdx.y;
    int kg0 = blockIdx.x * KT;

    size_t qbase = (size_t)b * Sn * Dn;
    uint32_t qsm = (uint32_t)__cvta_generic_to_shared(Qb);

    // ---- preload Q iter 0 via cp.async: 64 rows x 64 halves = 512 x 16B ----
    {
        int row = tid >> 3, seg = tid & 7;
        const __half* src = g_Qf + qbase + (size_t)row * Dn + seg * 8;
        cpa16(qsm + (uint32_t)(row * QKS + seg * 8) * 2, src);
        cpa_commit();
    }

    // ---- stage K tile (single fp16) ----
    {
        size_t base = ((size_t)b * Sn + kg0) * Dn;
        const uint32_t* Kg = (const uint32_t*)&g_Kf[base];
        for (int i = tid; i < KT * 32; i += 512) {
            int row = i >> 5, p = i & 31;
            *(uint32_t*)&Ks[row * QKS + 2 * p] = Kg[row * 32 + p];
        }
    }

    int warp = tid >> 5, lane = tid & 31;
    int mw = warp & 3, nw = warp >> 2;
    int g = lane >> 2, t = lane & 3;
    int rw = mw * 16;

    // ldmatrix addresses
    uint32_t aOffHalves = (uint32_t)((rw + (lane & 15)) * QKS + ((lane >> 4) << 3));
    uint32_t ksmB = (uint32_t)__cvta_generic_to_shared(Ks)
                  + (uint32_t)(((nw * 32 + (lane & 7) + ((lane >> 4) << 3)) * QKS
                                + (((lane >> 3) & 1) << 3)) * 2);

    float z0[4], z1[4];
#pragma unroll
    for (int nt = 0; nt < 4; nt++) { z0[nt] = 0.0f; z1[nt] = 0.0f; }

    for (int qc = 0; qc < 32; qc++) {
        cpa_wait0();
        __syncthreads();   // Q[qc] ready everywhere; prev Es drain complete

        if (qc + 1 < 32) {   // prefetch Q[qc+1] into other buffer
            int nbuf = (qc + 1) & 1;
            size_t qoff = qbase + (size_t)(qc + 1) * QI * Dn;
            int row = tid >> 3, seg = tid & 7;
            const __half* src = g_Qf + qoff + (size_t)row * Dn + seg * 8;
            cpa16(qsm + (uint32_t)(nbuf * QBUF + row * QKS + seg * 8) * 2, src);
            cpa_commit();
        }

        int buf = qc & 1;
        uint32_t aH = qsm + (uint32_t)(buf * QBUF + aOffHalves) * 2;

        float acc[4][4];
#pragma unroll
        for (int nt = 0; nt < 4; nt++)
#pragma unroll
            for (int i = 0; i < 4; i++) acc[nt][i] = 0.0f;

#pragma unroll
        for (int ks = 0; ks < 4; ks++) {
            uint32_t kbB = ks * 32;
            uint32_t a0, a1, a2, a3;
            ldsm4(aH + kbB, a0, a1, a2, a3);
#pragma unroll
            for (int p = 0; p < 2; p++) {
                uint32_t bo = (uint32_t)(p * 16 * QKS * 2) + kbB;
                uint32_t b0, b1, b2, b3;
                ldsm4(ksmB + bo, b0, b1, b2, b3);
                mma_f16(acc[2 * p],     a0, a1, a2, a3, b0, b1);
                mma_f16(acc[2 * p + 1], a0, a1, a2, a3, b2, b3);
            }
        }

        // exp -> Es; Z from rounded values
        int rA = rw + g, rB = rA + 8;
#pragma unroll
        for (int nt = 0; nt < 4; nt++) {
            int c0 = nw * 32 + nt * 8 + 2 * t;
            float e0 = fminf(__expf(acc[nt][0] - SHIFT), ECLAMP);
            float e1 = fminf(__expf(acc[nt][1] - SHIFT), ECLAMP);
            float e2 = fminf(__expf(acc[nt][2] - SHIFT), ECLAMP);
            float e3 = fminf(__expf(acc[nt][3] - SHIFT), ECLAMP);
            __half2 h01 = __floats2half2_rn(e0, e1);
            __half2 h23 = __floats2half2_rn(e2, e3);
            *(__half2*)&Es[rA * ESW + c0] = h01;
            *(__half2*)&Es[rB * ESW + c0] = h23;
            float2 f01 = __half22float2(h01);
            float2 f23 = __half22float2(h23);
            z0[nt] += f01.x + f23.x;
            z1[nt] += f01.y + f23.y;
        }
        __syncthreads();

        // drain Es -> g_E : 64 rows x 256B = 1024 uint4
        {
#pragma unroll
            for (int j = 0; j < 2; j++) {
                int flat = tid + 512 * j;
                int r = flat >> 4, seg = flat & 15;
                uint4 v = *(const uint4*)&Es[r * ESW + seg * 8];
                *(uint4*)&g_E[((size_t)(b * Sn + qc * QI + r)) * Sn + kg0 + seg * 8] = v;
            }
        }
    }

    // ---- Z reduction ----
#pragma unroll
    for (int nt = 0; nt < 4; nt++) {
        z0[nt] += __shfl_xor_sync(0xffffffffu, z0[nt], 4);
        z0[nt] += __shfl_xor_sync(0xffffffffu, z0[nt], 8);
        z0[nt] += __shfl_xor_sync(0xffffffffu, z0[nt], 16);
        z1[nt] += __shfl_xor_sync(0xffffffffu, z1[nt], 4);
        z1[nt] += __shfl_xor_sync(0xffffffffu, z1[nt], 8);
        z1[nt] += __shfl_xor_sync(0xffffffffu, z1[nt], 16);
    }
    if (lane < 4) {
#pragma unroll
        for (int nt = 0; nt < 4; nt++) {
            zred[warp][nt * 8 + 2 * lane]     = z0[nt];
            zred[warp][nt * 8 + 2 * lane + 1] = z1[nt];
        }
    }
    __syncthreads();
    if (tid < 128) {
        int c = tid;
        float Z = 0.0f;
#pragma unroll
        for (int m = 0; m < 4; m++) Z += zred[(c >> 5) * 4 + m][c & 31];
        int kg = b * Sn + kg0 + c;
        g_t[kg] = g_u[kg] / Z;
    }
}

// ---------------- K3: memory-bound GEMV ----------------
__global__ void k_gemv(const float* __restrict__ bfp, float* __restrict__ out) {
    __shared__ float ts[Sn];
    int tid = threadIdx.x;
    int b = blockIdx.y;
    int q0 = blockIdx.x * 32;

    for (int i = tid; i < Sn; i += 256) ts[i] = g_t[b * Sn + i];
    __syncthreads();

    int warp = tid >> 5, lane = tid & 31;
    float bias = bfp[0];

#pragma unroll
    for (int rr = 0; rr < 4; rr++) {
        int q = q0 + warp * 4 + rr;
        const uint4* Erow = (const uint4*)&g_E[((size_t)b * Sn + q) * Sn];
        float acc = 0.0f;
#pragma unroll
        for (int j = 0; j < 8; j++) {
            uint4 v = Erow[j * 32 + lane];
            const float2* tp = (const float2*)&ts[j * 256 + lane * 8];
            float2 f, tt;
            f = __half22float2(*(__half2*)&v.x); tt = tp[0]; acc += f.x * tt.x + f.y * tt.y;
            f = __half22float2(*(__half2*)&v.y); tt = tp[1]; acc += f.x * tt.x + f.y * tt.y;
            f = __half22float2(*(__half2*)&v.z); tt = tp[2]; acc += f.x * tt.x + f.y * tt.y;
            f = __half22float2(*(__half2*)&v.w); tt = tp[3]; acc += f.x * tt.x + f.y * tt.y;
        }
        acc += __shfl_xor_sync(0xffffffffu, acc, 16);
        acc += __shfl_xor_sync(0xffffffffu, acc, 8);
        acc += __shfl_xor_sync(0xffffffffu, acc, 4);
        acc += __shfl_xor_sync(0xffffffffu, acc, 2);
        acc += __shfl_xor_sync(0xffffffffu, acc, 1);
        if (lane == 0) out[b * Sn + q] = acc + bias;
    }
}

extern "C" void kernel_launch(void* const* d_in, const int* in_sizes, int n_in,
                              void* d_out, int out_size) {
    (void)in_sizes; (void)n_in; (void)out_size;
    const float* x  = (const float*)d_in[0];
    const float* Wq = (const float*)d_in[1];
    const float* Wk = (const float*)d_in[2];
    const float* Wv = (const float*)d_in[3];
    const float* Wf = (const float*)d_in[4];
    const float* bf = (const float*)d_in[5];
    float* out = (float*)d_out;

    const int smem_k1 = (2 * 128 * NPAD + 2 * NPAD * NPAD) * (int)sizeof(__nv_bfloat16);
    const int smem_k2 = (KT * QKS + 2 * QBUF + QI * ESW) * (int)sizeof(__half);
    cudaFuncSetAttribute(k_qku, cudaFuncAttributeMaxDynamicSharedMemorySize, smem_k1);
    cudaFuncSetAttribute(k_zt7, cudaFuncAttributeMaxDynamicSharedMemorySize, smem_k2);

    k_pe<<<(Sn * (Hn / 2) + 255) / 256, 256>>>();
    k_wcat<<<(NPAD * Hn + 255) / 256, 256>>>(Wq, Wk, Wv, Wf);
    k_qku<<<Bn * Sn / 128, 256, smem_k1>>>(x);
    k_zt7<<<dim3(Sn / KT, Bn), 512, smem_k2>>>();
    k_gemv<<<dim3(Sn / 32, Bn), 256>>>(bf, out);
}